// round 5
// baseline (speedup 1.0000x reference)
#include <cuda_runtime.h>

#define DD 64
#define HH 128
#define MAX_NODES 50000
#define MAX_COLORS 256

// Scratch: per-node / per-color MLP outputs (static device globals; no allocation).
__device__ float g_hv[MAX_NODES * DD];
__device__ float g_hc[MAX_COLORS * DD];

// ---------------------------------------------------------------------------
// MLP: out[n,64] = relu(x[n,64] @ W1[64,128] + b1) @ W2[128,64] + b2
// Block = 128 threads, 32 nodes per block. Weights staged in smem.
// Stage A: thread tid owns hidden unit j=tid for all 32 nodes (acc[32]).
// Stage B: thread owns output col j2=tid&63 for 16 nodes (acc[16]).
// hsT stored [hidden][node] with stride 36 (16B-aligned, limits STS conflicts).
// ---------------------------------------------------------------------------
__global__ __launch_bounds__(128, 2) void mlp_kernel(
    const float* __restrict__ x,
    const float* __restrict__ W1, const float* __restrict__ b1,
    const float* __restrict__ W2, const float* __restrict__ b2,
    float* __restrict__ out, int n)
{
    extern __shared__ float sm[];
    float* W1s = sm;                 // 64*128 = 8192
    float* W2s = W1s + 8192;         // 128*64 = 8192
    float* xsT = W2s + 8192;         // [k][m], stride 32 -> 2048
    float* hsT = xsT + 2048;         // [j][m], stride 36 -> 4608
    float* b1s = hsT + 4608;         // 128
    float* b2s = b1s + 128;          // 64

    const int tid = threadIdx.x;
    const int node0 = blockIdx.x * 32;

    // ---- cooperative loads ----
    {
        const float4* s1 = (const float4*)W1;
        const float4* s2 = (const float4*)W2;
        float4* d1 = (float4*)W1s;
        float4* d2 = (float4*)W2s;
        #pragma unroll
        for (int i = tid; i < 2048; i += 128) { d1[i] = s1[i]; d2[i] = s2[i]; }
        b1s[tid] = b1[tid];
        if (tid < 64) b2s[tid] = b2[tid];
        // transposed x tile (zero-padded past n)
        for (int i = tid; i < 2048; i += 128) {
            int m = i & 31, k = i >> 5;
            int node = node0 + m;
            float v = 0.0f;
            if (node < n) v = x[node * DD + k];
            xsT[k * 32 + m] = v;
        }
    }
    __syncthreads();

    // ---- stage A: hidden = relu(x @ W1 + b1) ----
    {
        float acc[32];
        const float bj = b1s[tid];
        #pragma unroll
        for (int m = 0; m < 32; m++) acc[m] = bj;
        #pragma unroll 2
        for (int k = 0; k < DD; k++) {
            const float w = W1s[k * HH + tid];
            const float4* xp = (const float4*)(xsT + k * 32);
            #pragma unroll
            for (int q = 0; q < 8; q++) {
                float4 xv = xp[q];
                acc[4*q+0] = fmaf(xv.x, w, acc[4*q+0]);
                acc[4*q+1] = fmaf(xv.y, w, acc[4*q+1]);
                acc[4*q+2] = fmaf(xv.z, w, acc[4*q+2]);
                acc[4*q+3] = fmaf(xv.w, w, acc[4*q+3]);
            }
        }
        #pragma unroll
        for (int m = 0; m < 32; m++) hsT[tid * 36 + m] = fmaxf(acc[m], 0.0f);
    }
    __syncthreads();

    // ---- stage B: out = hidden @ W2 + b2 ----
    {
        const int j2 = tid & 63;
        const int h  = tid >> 6;            // warp-uniform (warps 0,1 -> 0; 2,3 -> 1)
        float acc[16];
        const float bj = b2s[j2];
        #pragma unroll
        for (int m = 0; m < 16; m++) acc[m] = bj;
        #pragma unroll 2
        for (int k = 0; k < HH; k++) {
            const float w = W2s[k * 64 + j2];
            const float4* hp = (const float4*)(hsT + k * 36 + h * 16);
            #pragma unroll
            for (int q = 0; q < 4; q++) {
                float4 hv = hp[q];
                acc[4*q+0] = fmaf(hv.x, w, acc[4*q+0]);
                acc[4*q+1] = fmaf(hv.y, w, acc[4*q+1]);
                acc[4*q+2] = fmaf(hv.z, w, acc[4*q+2]);
                acc[4*q+3] = fmaf(hv.w, w, acc[4*q+3]);
            }
        }
        #pragma unroll
        for (int m = 0; m < 16; m++) {
            int node = node0 + h * 16 + m;
            if (node < n) out[node * DD + j2] = acc[m];
        }
    }
}

// ---------------------------------------------------------------------------
// Scatter: out[dst[e]][:] += h[src[e]][:]  — 16 threads/edge, one red.v4 each.
// ---------------------------------------------------------------------------
__global__ void scatter_kernel(const float* __restrict__ h,
                               const int* __restrict__ src,
                               const int* __restrict__ dst,
                               float* __restrict__ out, int nE)
{
    int gid = blockIdx.x * blockDim.x + threadIdx.x;
    int e = gid >> 4;
    if (e >= nE) return;
    int c = gid & 15;
    int s = __ldg(src + e);
    int d = __ldg(dst + e);
    float4 v = __ldg((const float4*)(h + (size_t)s * DD) + c);
    float* p = out + (size_t)d * DD + (size_t)c * 4;
    asm volatile("red.global.add.v4.f32 [%0], {%1, %2, %3, %4};"
                 :: "l"(p), "f"(v.x), "f"(v.y), "f"(v.z), "f"(v.w)
                 : "memory");
}

// ---------------------------------------------------------------------------
// Zero + epilogue
// ---------------------------------------------------------------------------
__global__ void zero_kernel(float4* __restrict__ out, int n4)
{
    int i = blockIdx.x * blockDim.x + threadIdx.x;
    if (i < n4) out[i] = make_float4(0.f, 0.f, 0.f, 0.f);
}

__global__ void finalize_kernel(const float4* __restrict__ x,
                                float4* __restrict__ out, int n4)
{
    int i = blockIdx.x * blockDim.x + threadIdx.x;
    if (i >= n4) return;
    float4 a = __ldg(x + i);
    float4 b = out[i];
    b.x = fmaxf(a.x + b.x, 0.f);
    b.y = fmaxf(a.y + b.y, 0.f);
    b.z = fmaxf(a.z + b.z, 0.f);
    b.w = fmaxf(a.w + b.w, 0.f);
    out[i] = b;
}

// ---------------------------------------------------------------------------
extern "C" void kernel_launch(void* const* d_in, const int* in_sizes, int n_in,
                              void* d_out, int out_size)
{
    const float* x_v  = (const float*)d_in[0];
    const float* x_c  = (const float*)d_in[1];
    const float* W1v  = (const float*)d_in[2];
    const float* b1v  = (const float*)d_in[3];
    const float* W2v  = (const float*)d_in[4];
    const float* b2v  = (const float*)d_in[5];
    const float* W1c  = (const float*)d_in[6];
    const float* b1c  = (const float*)d_in[7];
    const float* W2c  = (const float*)d_in[8];
    const float* b2c  = (const float*)d_in[9];
    const int* src_vv = (const int*)d_in[10];
    const int* dst_vv = (const int*)d_in[11];
    const int* src_vc = (const int*)d_in[12];
    const int* dst_vc = (const int*)d_in[13];

    const int n_nodes  = in_sizes[0] / DD;
    const int n_colors = in_sizes[1] / DD;
    const int n_vv = in_sizes[10];
    const int n_vc = in_sizes[12];

    float* hv = nullptr;
    float* hc = nullptr;
    cudaGetSymbolAddress((void**)&hv, g_hv);
    cudaGetSymbolAddress((void**)&hc, g_hc);

    const int smem_bytes = (8192 + 8192 + 2048 + 4608 + 128 + 64) * (int)sizeof(float); // 92928
    cudaFuncSetAttribute(mlp_kernel, cudaFuncAttributeMaxDynamicSharedMemorySize, smem_bytes);

    float* out = (float*)d_out;
    const int n4 = out_size / 4;

    zero_kernel<<<(n4 + 255) / 256, 256>>>((float4*)out, n4);

    mlp_kernel<<<(n_colors + 31) / 32, 128, smem_bytes>>>(x_c, W1c, b1c, W2c, b2c, hc, n_colors);
    mlp_kernel<<<(n_nodes  + 31) / 32, 128, smem_bytes>>>(x_v, W1v, b1v, W2v, b2v, hv, n_nodes);

    {
        long t = (long)n_vv * 16;
        scatter_kernel<<<(int)((t + 255) / 256), 256>>>(hv, src_vv, dst_vv, out, n_vv);
    }
    {
        long t = (long)n_vc * 16;
        scatter_kernel<<<(int)((t + 255) / 256), 256>>>(hc, src_vc, dst_vc, out, n_vc);
    }

    finalize_kernel<<<(n4 + 255) / 256, 256>>>((const float4*)x_v, (float4*)out, n4);
}

// round 6
// speedup vs baseline: 1.0002x; 1.0002x over previous
#include <cuda_runtime.h>

#define DD 64
#define HH 128
#define MAX_NODES 50000
#define MAX_COLORS 256

// Scratch: per-node / per-color MLP outputs (static device globals; no allocation).
__device__ float g_hv[MAX_NODES * DD];
__device__ float g_hc[MAX_COLORS * DD];

// ---------------------------------------------------------------------------
// MLP: out[n,64] = relu(x[n,64] @ W1[64,128] + b1) @ W2[128,64] + b2
// Block = 128 threads, 32 nodes per block. Weights staged in smem.
// Stage A: thread tid owns hidden unit j=tid for all 32 nodes (acc[32]).
// Stage B: thread owns output col j2=tid&63 for 16 nodes (acc[16]).
// hsT stored [hidden][node] with stride 36 (16B-aligned, limits STS conflicts).
// ---------------------------------------------------------------------------
__global__ __launch_bounds__(128, 2) void mlp_kernel(
    const float* __restrict__ x,
    const float* __restrict__ W1, const float* __restrict__ b1,
    const float* __restrict__ W2, const float* __restrict__ b2,
    float* __restrict__ out, int n)
{
    extern __shared__ float sm[];
    float* W1s = sm;                 // 64*128 = 8192
    float* W2s = W1s + 8192;         // 128*64 = 8192
    float* xsT = W2s + 8192;         // [k][m], stride 32 -> 2048
    float* hsT = xsT + 2048;         // [j][m], stride 36 -> 4608
    float* b1s = hsT + 4608;         // 128
    float* b2s = b1s + 128;          // 64

    const int tid = threadIdx.x;
    const int node0 = blockIdx.x * 32;

    // ---- cooperative loads ----
    {
        const float4* s1 = (const float4*)W1;
        const float4* s2 = (const float4*)W2;
        float4* d1 = (float4*)W1s;
        float4* d2 = (float4*)W2s;
        #pragma unroll
        for (int i = tid; i < 2048; i += 128) { d1[i] = s1[i]; d2[i] = s2[i]; }
        b1s[tid] = b1[tid];
        if (tid < 64) b2s[tid] = b2[tid];
        // transposed x tile (zero-padded past n)
        for (int i = tid; i < 2048; i += 128) {
            int m = i & 31, k = i >> 5;
            int node = node0 + m;
            float v = 0.0f;
            if (node < n) v = x[node * DD + k];
            xsT[k * 32 + m] = v;
        }
    }
    __syncthreads();

    // ---- stage A: hidden = relu(x @ W1 + b1) ----
    {
        float acc[32];
        const float bj = b1s[tid];
        #pragma unroll
        for (int m = 0; m < 32; m++) acc[m] = bj;
        #pragma unroll 2
        for (int k = 0; k < DD; k++) {
            const float w = W1s[k * HH + tid];
            const float4* xp = (const float4*)(xsT + k * 32);
            #pragma unroll
            for (int q = 0; q < 8; q++) {
                float4 xv = xp[q];
                acc[4*q+0] = fmaf(xv.x, w, acc[4*q+0]);
                acc[4*q+1] = fmaf(xv.y, w, acc[4*q+1]);
                acc[4*q+2] = fmaf(xv.z, w, acc[4*q+2]);
                acc[4*q+3] = fmaf(xv.w, w, acc[4*q+3]);
            }
        }
        #pragma unroll
        for (int m = 0; m < 32; m++) hsT[tid * 36 + m] = fmaxf(acc[m], 0.0f);
    }
    __syncthreads();

    // ---- stage B: out = hidden @ W2 + b2 ----
    {
        const int j2 = tid & 63;
        const int h  = tid >> 6;            // warp-uniform (warps 0,1 -> 0; 2,3 -> 1)
        float acc[16];
        const float bj = b2s[j2];
        #pragma unroll
        for (int m = 0; m < 16; m++) acc[m] = bj;
        #pragma unroll 2
        for (int k = 0; k < HH; k++) {
            const float w = W2s[k * 64 + j2];
            const float4* hp = (const float4*)(hsT + k * 36 + h * 16);
            #pragma unroll
            for (int q = 0; q < 4; q++) {
                float4 hv = hp[q];
                acc[4*q+0] = fmaf(hv.x, w, acc[4*q+0]);
                acc[4*q+1] = fmaf(hv.y, w, acc[4*q+1]);
                acc[4*q+2] = fmaf(hv.z, w, acc[4*q+2]);
                acc[4*q+3] = fmaf(hv.w, w, acc[4*q+3]);
            }
        }
        #pragma unroll
        for (int m = 0; m < 16; m++) {
            int node = node0 + h * 16 + m;
            if (node < n) out[node * DD + j2] = acc[m];
        }
    }
}

// ---------------------------------------------------------------------------
// Scatter: out[dst[e]][:] += h[src[e]][:]  — 16 threads/edge, one red.v4 each.
// ---------------------------------------------------------------------------
__global__ void scatter_kernel(const float* __restrict__ h,
                               const int* __restrict__ src,
                               const int* __restrict__ dst,
                               float* __restrict__ out, int nE)
{
    int gid = blockIdx.x * blockDim.x + threadIdx.x;
    int e = gid >> 4;
    if (e >= nE) return;
    int c = gid & 15;
    int s = __ldg(src + e);
    int d = __ldg(dst + e);
    float4 v = __ldg((const float4*)(h + (size_t)s * DD) + c);
    float* p = out + (size_t)d * DD + (size_t)c * 4;
    asm volatile("red.global.add.v4.f32 [%0], {%1, %2, %3, %4};"
                 :: "l"(p), "f"(v.x), "f"(v.y), "f"(v.z), "f"(v.w)
                 : "memory");
}

// ---------------------------------------------------------------------------
// Zero + epilogue
// ---------------------------------------------------------------------------
__global__ void zero_kernel(float4* __restrict__ out, int n4)
{
    int i = blockIdx.x * blockDim.x + threadIdx.x;
    if (i < n4) out[i] = make_float4(0.f, 0.f, 0.f, 0.f);
}

__global__ void finalize_kernel(const float4* __restrict__ x,
                                float4* __restrict__ out, int n4)
{
    int i = blockIdx.x * blockDim.x + threadIdx.x;
    if (i >= n4) return;
    float4 a = __ldg(x + i);
    float4 b = out[i];
    b.x = fmaxf(a.x + b.x, 0.f);
    b.y = fmaxf(a.y + b.y, 0.f);
    b.z = fmaxf(a.z + b.z, 0.f);
    b.w = fmaxf(a.w + b.w, 0.f);
    out[i] = b;
}

// ---------------------------------------------------------------------------
extern "C" void kernel_launch(void* const* d_in, const int* in_sizes, int n_in,
                              void* d_out, int out_size)
{
    const float* x_v  = (const float*)d_in[0];
    const float* x_c  = (const float*)d_in[1];
    const float* W1v  = (const float*)d_in[2];
    const float* b1v  = (const float*)d_in[3];
    const float* W2v  = (const float*)d_in[4];
    const float* b2v  = (const float*)d_in[5];
    const float* W1c  = (const float*)d_in[6];
    const float* b1c  = (const float*)d_in[7];
    const float* W2c  = (const float*)d_in[8];
    const float* b2c  = (const float*)d_in[9];
    const int* src_vv = (const int*)d_in[10];
    const int* dst_vv = (const int*)d_in[11];
    const int* src_vc = (const int*)d_in[12];
    const int* dst_vc = (const int*)d_in[13];

    const int n_nodes  = in_sizes[0] / DD;
    const int n_colors = in_sizes[1] / DD;
    const int n_vv = in_sizes[10];
    const int n_vc = in_sizes[12];

    float* hv = nullptr;
    float* hc = nullptr;
    cudaGetSymbolAddress((void**)&hv, g_hv);
    cudaGetSymbolAddress((void**)&hc, g_hc);

    const int smem_bytes = (8192 + 8192 + 2048 + 4608 + 128 + 64) * (int)sizeof(float); // 92928
    cudaFuncSetAttribute(mlp_kernel, cudaFuncAttributeMaxDynamicSharedMemorySize, smem_bytes);

    float* out = (float*)d_out;
    const int n4 = out_size / 4;

    zero_kernel<<<(n4 + 255) / 256, 256>>>((float4*)out, n4);

    mlp_kernel<<<(n_colors + 31) / 32, 128, smem_bytes>>>(x_c, W1c, b1c, W2c, b2c, hc, n_colors);
    mlp_kernel<<<(n_nodes  + 31) / 32, 128, smem_bytes>>>(x_v, W1v, b1v, W2v, b2v, hv, n_nodes);

    {
        long t = (long)n_vv * 16;
        scatter_kernel<<<(int)((t + 255) / 256), 256>>>(hv, src_vv, dst_vv, out, n_vv);
    }
    {
        long t = (long)n_vc * 16;
        scatter_kernel<<<(int)((t + 255) / 256), 256>>>(hc, src_vc, dst_vc, out, n_vc);
    }

    finalize_kernel<<<(n4 + 255) / 256, 256>>>((const float4*)x_v, (float4*)out, n4);
}

// round 7
// speedup vs baseline: 1.0107x; 1.0105x over previous
#include <cuda_runtime.h>

#define DD 64
#define HH 128
#define MAX_NODES 50000
#define MAX_COLORS 256

// Scratch: per-node / per-color MLP outputs (static device globals; no allocation).
__device__ float g_hv[MAX_NODES * DD];
__device__ float g_hc[MAX_COLORS * DD];

// ---------------------------------------------------------------------------
// MLP: out[n,64] = relu(x[n,64] @ W1[64,128] + b1) @ W2[128,64] + b2
// Block = 128 threads, 32 nodes per block. Weights staged in smem.
// Stage A: thread tid owns hidden unit j=tid for all 32 nodes (acc[32]).
// Stage B: thread owns output col j2=tid&63 for 16 nodes (acc[16]).
// hsT stored [hidden][node] with stride 36 (16B-aligned, limits STS conflicts).
// ---------------------------------------------------------------------------
__global__ __launch_bounds__(128, 2) void mlp_kernel(
    const float* __restrict__ x,
    const float* __restrict__ W1, const float* __restrict__ b1,
    const float* __restrict__ W2, const float* __restrict__ b2,
    float* __restrict__ out, int n)
{
    extern __shared__ float sm[];
    float* W1s = sm;                 // 64*128 = 8192
    float* W2s = W1s + 8192;         // 128*64 = 8192
    float* xsT = W2s + 8192;         // [k][m], stride 32 -> 2048
    float* hsT = xsT + 2048;         // [j][m], stride 36 -> 4608
    float* b1s = hsT + 4608;         // 128
    float* b2s = b1s + 128;          // 64

    const int tid = threadIdx.x;
    const int node0 = blockIdx.x * 32;

    // ---- cooperative loads ----
    {
        const float4* s1 = (const float4*)W1;
        const float4* s2 = (const float4*)W2;
        float4* d1 = (float4*)W1s;
        float4* d2 = (float4*)W2s;
        #pragma unroll
        for (int i = tid; i < 2048; i += 128) { d1[i] = s1[i]; d2[i] = s2[i]; }
        b1s[tid] = b1[tid];
        if (tid < 64) b2s[tid] = b2[tid];
        // transposed x tile (zero-padded past n)
        for (int i = tid; i < 2048; i += 128) {
            int m = i & 31, k = i >> 5;
            int node = node0 + m;
            float v = 0.0f;
            if (node < n) v = x[node * DD + k];
            xsT[k * 32 + m] = v;
        }
    }
    __syncthreads();

    // ---- stage A: hidden = relu(x @ W1 + b1) ----
    {
        float acc[32];
        const float bj = b1s[tid];
        #pragma unroll
        for (int m = 0; m < 32; m++) acc[m] = bj;
        #pragma unroll 2
        for (int k = 0; k < DD; k++) {
            const float w = W1s[k * HH + tid];
            const float4* xp = (const float4*)(xsT + k * 32);
            #pragma unroll
            for (int q = 0; q < 8; q++) {
                float4 xv = xp[q];
                acc[4*q+0] = fmaf(xv.x, w, acc[4*q+0]);
                acc[4*q+1] = fmaf(xv.y, w, acc[4*q+1]);
                acc[4*q+2] = fmaf(xv.z, w, acc[4*q+2]);
                acc[4*q+3] = fmaf(xv.w, w, acc[4*q+3]);
            }
        }
        #pragma unroll
        for (int m = 0; m < 32; m++) hsT[tid * 36 + m] = fmaxf(acc[m], 0.0f);
    }
    __syncthreads();

    // ---- stage B: out = hidden @ W2 + b2 ----
    {
        const int j2 = tid & 63;
        const int h  = tid >> 6;            // warp-uniform (warps 0,1 -> 0; 2,3 -> 1)
        float acc[16];
        const float bj = b2s[j2];
        #pragma unroll
        for (int m = 0; m < 16; m++) acc[m] = bj;
        #pragma unroll 2
        for (int k = 0; k < HH; k++) {
            const float w = W2s[k * 64 + j2];
            const float4* hp = (const float4*)(hsT + k * 36 + h * 16);
            #pragma unroll
            for (int q = 0; q < 4; q++) {
                float4 hv = hp[q];
                acc[4*q+0] = fmaf(hv.x, w, acc[4*q+0]);
                acc[4*q+1] = fmaf(hv.y, w, acc[4*q+1]);
                acc[4*q+2] = fmaf(hv.z, w, acc[4*q+2]);
                acc[4*q+3] = fmaf(hv.w, w, acc[4*q+3]);
            }
        }
        #pragma unroll
        for (int m = 0; m < 16; m++) {
            int node = node0 + h * 16 + m;
            if (node < n) out[node * DD + j2] = acc[m];
        }
    }
}

// ---------------------------------------------------------------------------
// Scatter: out[dst[e]][:] += h[src[e]][:]  — 16 threads/edge, one red.v4 each.
// ---------------------------------------------------------------------------
__global__ void scatter_kernel(const float* __restrict__ h,
                               const int* __restrict__ src,
                               const int* __restrict__ dst,
                               float* __restrict__ out, int nE)
{
    int gid = blockIdx.x * blockDim.x + threadIdx.x;
    int e = gid >> 4;
    if (e >= nE) return;
    int c = gid & 15;
    int s = __ldg(src + e);
    int d = __ldg(dst + e);
    float4 v = __ldg((const float4*)(h + (size_t)s * DD) + c);
    float* p = out + (size_t)d * DD + (size_t)c * 4;
    asm volatile("red.global.add.v4.f32 [%0], {%1, %2, %3, %4};"
                 :: "l"(p), "f"(v.x), "f"(v.y), "f"(v.z), "f"(v.w)
                 : "memory");
}

// ---------------------------------------------------------------------------
// Zero + epilogue
// ---------------------------------------------------------------------------
__global__ void zero_kernel(float4* __restrict__ out, int n4)
{
    int i = blockIdx.x * blockDim.x + threadIdx.x;
    if (i < n4) out[i] = make_float4(0.f, 0.f, 0.f, 0.f);
}

__global__ void finalize_kernel(const float4* __restrict__ x,
                                float4* __restrict__ out, int n4)
{
    int i = blockIdx.x * blockDim.x + threadIdx.x;
    if (i >= n4) return;
    float4 a = __ldg(x + i);
    float4 b = out[i];
    b.x = fmaxf(a.x + b.x, 0.f);
    b.y = fmaxf(a.y + b.y, 0.f);
    b.z = fmaxf(a.z + b.z, 0.f);
    b.w = fmaxf(a.w + b.w, 0.f);
    out[i] = b;
}

// ---------------------------------------------------------------------------
extern "C" void kernel_launch(void* const* d_in, const int* in_sizes, int n_in,
                              void* d_out, int out_size)
{
    const float* x_v  = (const float*)d_in[0];
    const float* x_c  = (const float*)d_in[1];
    const float* W1v  = (const float*)d_in[2];
    const float* b1v  = (const float*)d_in[3];
    const float* W2v  = (const float*)d_in[4];
    const float* b2v  = (const float*)d_in[5];
    const float* W1c  = (const float*)d_in[6];
    const float* b1c  = (const float*)d_in[7];
    const float* W2c  = (const float*)d_in[8];
    const float* b2c  = (const float*)d_in[9];
    const int* src_vv = (const int*)d_in[10];
    const int* dst_vv = (const int*)d_in[11];
    const int* src_vc = (const int*)d_in[12];
    const int* dst_vc = (const int*)d_in[13];

    const int n_nodes  = in_sizes[0] / DD;
    const int n_colors = in_sizes[1] / DD;
    const int n_vv = in_sizes[10];
    const int n_vc = in_sizes[12];

    float* hv = nullptr;
    float* hc = nullptr;
    cudaGetSymbolAddress((void**)&hv, g_hv);
    cudaGetSymbolAddress((void**)&hc, g_hc);

    const int smem_bytes = (8192 + 8192 + 2048 + 4608 + 128 + 64) * (int)sizeof(float); // 92928
    cudaFuncSetAttribute(mlp_kernel, cudaFuncAttributeMaxDynamicSharedMemorySize, smem_bytes);

    float* out = (float*)d_out;
    const int n4 = out_size / 4;

    zero_kernel<<<(n4 + 255) / 256, 256>>>((float4*)out, n4);

    mlp_kernel<<<(n_colors + 31) / 32, 128, smem_bytes>>>(x_c, W1c, b1c, W2c, b2c, hc, n_colors);
    mlp_kernel<<<(n_nodes  + 31) / 32, 128, smem_bytes>>>(x_v, W1v, b1v, W2v, b2v, hv, n_nodes);

    {
        long t = (long)n_vv * 16;
        scatter_kernel<<<(int)((t + 255) / 256), 256>>>(hv, src_vv, dst_vv, out, n_vv);
    }
    {
        long t = (long)n_vc * 16;
        scatter_kernel<<<(int)((t + 255) / 256), 256>>>(hc, src_vc, dst_vc, out, n_vc);
    }

    finalize_kernel<<<(n4 + 255) / 256, 256>>>((const float4*)x_v, (float4*)out, n4);
}